// round 3
// baseline (speedup 1.0000x reference)
#include <cuda_runtime.h>

// HashEncoding (instant-NGP style multires hash grid), sm_103a.
// N points (1M), 16 levels, table 2^19 entries x 2 float features per level.
//
// Thread = (point, level). lane&15 = level, so a warp covers 2 points x 16
// levels and writes 256B of contiguous output. Each thread does 8 random
// float2 gathers from its level's 4MB table (all 16 tables = 64MB, L2-resident).
//
// Numerics: the XLA-GPU reference lowers the f32 division corners/res to the
// non-IEEE fast path (div.full.f32). We must reproduce those exact bits or
// ~0.2% of quantized hash coords land on the other side of the truncation
// boundary (observed rel_err 6.6e-2 with div.rn). Power-of-two resolutions
// are exact under both, so only the 13 non-pow2 levels were affected.

#define TABLE_SIZE (1u << 19)
#define HASH_MASK  (TABLE_SIZE - 1u)
#define P1 2654435761u
#define P2 805459861u

// int(16 * 32**(i/15)) with the host libm pow: level 9 = 127 (pow(32,0.6)
// returns just below 8.0 -- empirically confirmed: forcing 128 fully
// decorrelated level 9).
__constant__ int d_res[16] = {16, 20, 25, 32, 40, 50, 64, 80,
                              101, 127, 161, 203, 256, 322, 406, 512};

// q = trunc( ((c/res + 1) * 0.5) * 2^18 ), with the division done as
// div.full.f32 to match XLA-GPU's lowering. The *0.5 and *2^18 are exact
// powers of two, so one rounded add + exact multiply reproduces the chain.
__device__ __forceinline__ unsigned qval(int c, float resf) {
    float d;
    asm("div.full.f32 %0, %1, %2;" : "=f"(d) : "f"((float)c), "f"(resf));
    float v = __fmul_rn(__fadd_rn(d, 1.0f), 131072.0f);
    return (unsigned)v;  // truncation toward zero, value in [131072, 262144)
}

__global__ __launch_bounds__(256)
void hash_encoding_kernel(const float* __restrict__ x,
                          const float2* __restrict__ tables,
                          float2* __restrict__ out,
                          int n_pts)
{
    int tid = blockIdx.x * blockDim.x + threadIdx.x;
    int level = tid & 15;
    int point = tid >> 4;
    if (point >= n_pts) return;

    // 16 lanes per point read the same 12B -> L1/broadcast friendly.
    float px = fminf(fmaxf(__ldg(x + 3 * point + 0), -1.0f), 1.0f);
    float py = fminf(fmaxf(__ldg(x + 3 * point + 1), -1.0f), 1.0f);
    float pz = fminf(fmaxf(__ldg(x + 3 * point + 2), -1.0f), 1.0f);

    int res = d_res[level];
    float resf = (float)res;

    float cx = __fmul_rn(px, resf);
    float cy = __fmul_rn(py, resf);
    float cz = __fmul_rn(pz, resf);
    float fx = floorf(cx), fy = floorf(cy), fz = floorf(cz);
    float lx = __fsub_rn(cx, fx);
    float ly = __fsub_rn(cy, fy);
    float lz = __fsub_rn(cz, fz);
    int ix = (int)fx, iy = (int)fy, iz = (int)fz;

    // Python-style mod for values in [-res, res+1] via conditional +-res.
    int x0 = ix;     if (x0 < 0) x0 += res; else if (x0 >= res) x0 -= res;
    int x1 = ix + 1; if (x1 < 0) x1 += res; else if (x1 >= res) x1 -= res;
    int y0 = iy;     if (y0 < 0) y0 += res; else if (y0 >= res) y0 -= res;
    int y1 = iy + 1; if (y1 < 0) y1 += res; else if (y1 >= res) y1 -= res;
    int z0 = iz;     if (z0 < 0) z0 += res; else if (z0 >= res) z0 -= res;
    int z1 = iz + 1; if (z1 < 0) z1 += res; else if (z1 >= res) z1 -= res;

    // hash components; mod 2^19 commutes with 32-bit wraparound arithmetic.
    unsigned hx[2], hy[2], hz[2];
    hx[0] = qval(x0, resf);
    hx[1] = qval(x1, resf);
    hy[0] = qval(y0, resf) * P1;
    hy[1] = qval(y1, resf) * P1;
    hz[0] = qval(z0, resf) * P2;
    hz[1] = qval(z1, resf) * P2;

    const float2* tab = tables + (size_t)level * TABLE_SIZE;

    // Issue all 8 gathers up front for MLP.
    float2 f[8];
#pragma unroll
    for (int c = 0; c < 8; c++) {
        unsigned idx = (hx[(c >> 2) & 1] + hy[(c >> 1) & 1] + hz[c & 1]) & HASH_MASK;
        f[c] = __ldg(&tab[idx]);
    }

    float wx[2] = {1.0f - lx, lx};
    float wy[2] = {1.0f - ly, ly};
    float wz[2] = {1.0f - lz, lz};

    float ax = 0.0f, ay = 0.0f;
#pragma unroll
    for (int c = 0; c < 8; c++) {
        float w = wx[(c >> 2) & 1] * wy[(c >> 1) & 1] * wz[c & 1];
        ax += w * f[c].x;
        ay += w * f[c].y;
    }

    // out row = 32 floats = 16 float2; warp writes 256B contiguous.
    out[(size_t)point * 16 + level] = make_float2(ax, ay);
}

extern "C" void kernel_launch(void* const* d_in, const int* in_sizes, int n_in,
                              void* d_out, int out_size) {
    const float* x = (const float*)d_in[0];
    const float2* tables = (const float2*)d_in[1];
    float2* out = (float2*)d_out;
    int n_pts = in_sizes[0] / 3;
    long long total = (long long)n_pts * 16;
    int block = 256;
    int grid = (int)((total + block - 1) / block);
    hash_encoding_kernel<<<grid, block>>>(x, tables, out, n_pts);
}

// round 4
// speedup vs baseline: 1.1115x; 1.1115x over previous
#include <cuda_runtime.h>

// HashEncoding (instant-NGP multires hash grid), sm_103a.
// R3 profile: L1tex 94% (wavefront-bound), L2 75%, DRAM 5%.
// R4: precompute dense per-level corner grids for levels 0-8 (r<=101),
// storing the (z, z+1 mod r) feature pair as one aligned float4.
// Small-level lookups become 4x LDG.128 (4 sectors) instead of 8x LDG.64
// (8 sectors), and skip the hash entirely. Gather sectors: 128M -> 92M.

#define TABLE_SIZE (1u << 19)
#define HASH_MASK  (TABLE_SIZE - 1u)
#define P1 2654435761u
#define P2 805459861u
#define N_SMALL 9   // levels 0..8 use the dense grid

// int(16 * 32**(i/15)) with host libm pow: level 9 = 127 (empirically confirmed).
__constant__ int d_res[16] = {16, 20, 25, 32, 40, 50, 64, 80,
                              101, 127, 161, 203, 256, 322, 406, 512};

// start offset (in float4 units) of each small level's dense r^3 grid
__constant__ int d_start[N_SMALL] = {0, 4096, 12096, 27721, 60489,
                                     124489, 249489, 511633, 1023633};
#define DENSE_TOTAL 2053934  // sum of r^3 for levels 0..8

__device__ float4 g_dense[DENSE_TOTAL];  // ~33 MB static scratch

// q = trunc( ((c/res + 1) * 0.5) * 2^18 ), division as div.full.f32 to match
// the XLA-GPU reference's non-IEEE fast-path lowering (bit-exact requirement).
__device__ __forceinline__ unsigned qval(int c, float resf) {
    float d;
    asm("div.full.f32 %0, %1, %2;" : "=f"(d) : "f"((float)c), "f"(resf));
    float v = __fmul_rn(__fadd_rn(d, 1.0f), 131072.0f);
    return (unsigned)v;
}

// Build dense grids: entry (a,b,c) = (tables[hash(a,b,c)], tables[hash(a,b,(c+1)%r)]).
__global__ void precompute_dense(const float2* __restrict__ tables) {
    int level = blockIdx.y;
    int r = d_res[level];
    int n = r * r * r;
    int i = blockIdx.x * blockDim.x + threadIdx.x;
    if (i >= n) return;
    int c = i % r;
    int t = i / r;
    int b = t % r;
    int a = t / r;
    float resf = (float)r;
    unsigned ha = qval(a, resf);
    unsigned hb = qval(b, resf) * P1;
    unsigned hc0 = qval(c, resf) * P2;
    int c1 = (c + 1 == r) ? 0 : c + 1;
    unsigned hc1 = qval(c1, resf) * P2;
    const float2* tab = tables + (size_t)level * TABLE_SIZE;
    float2 f0 = __ldg(&tab[(ha + hb + hc0) & HASH_MASK]);
    float2 f1 = __ldg(&tab[(ha + hb + hc1) & HASH_MASK]);
    g_dense[d_start[level] + i] = make_float4(f0.x, f0.y, f1.x, f1.y);
}

__global__ __launch_bounds__(256)
void hash_encoding_kernel(const float* __restrict__ x,
                          const float2* __restrict__ tables,
                          float2* __restrict__ out,
                          int n_pts)
{
    int tid = blockIdx.x * blockDim.x + threadIdx.x;
    int level = tid & 15;
    int point = tid >> 4;
    if (point >= n_pts) return;

    float px = fminf(fmaxf(__ldg(x + 3 * point + 0), -1.0f), 1.0f);
    float py = fminf(fmaxf(__ldg(x + 3 * point + 1), -1.0f), 1.0f);
    float pz = fminf(fmaxf(__ldg(x + 3 * point + 2), -1.0f), 1.0f);

    int res = d_res[level];
    float resf = (float)res;

    float cx = __fmul_rn(px, resf);
    float cy = __fmul_rn(py, resf);
    float cz = __fmul_rn(pz, resf);
    float fx = floorf(cx), fy = floorf(cy), fz = floorf(cz);
    float lx = __fsub_rn(cx, fx);
    float ly = __fsub_rn(cy, fy);
    float lz = __fsub_rn(cz, fz);
    int ix = (int)fx, iy = (int)fy, iz = (int)fz;

    // Python-style mod for values in [-res, res+1].
    int x0 = ix;     if (x0 < 0) x0 += res; else if (x0 >= res) x0 -= res;
    int x1 = ix + 1; if (x1 < 0) x1 += res; else if (x1 >= res) x1 -= res;
    int y0 = iy;     if (y0 < 0) y0 += res; else if (y0 >= res) y0 -= res;
    int y1 = iy + 1; if (y1 < 0) y1 += res; else if (y1 >= res) y1 -= res;
    int z0 = iz;     if (z0 < 0) z0 += res; else if (z0 >= res) z0 -= res;

    float wx1 = lx, wx0 = 1.0f - lx;
    float wy1 = ly, wy0 = 1.0f - ly;
    float wz1 = lz, wz0 = 1.0f - lz;

    float ax, ay;

    if (level < N_SMALL) {
        // Dense path: 4 aligned 16B gathers, no hashing.
        const float4* g = g_dense + d_start[level];
        int bx0 = x0 * res, bx1 = x1 * res;
        float4 v00 = __ldg(&g[(bx0 + y0) * res + z0]);
        float4 v01 = __ldg(&g[(bx0 + y1) * res + z0]);
        float4 v10 = __ldg(&g[(bx1 + y0) * res + z0]);
        float4 v11 = __ldg(&g[(bx1 + y1) * res + z0]);
        float w00 = wx0 * wy0, w01 = wx0 * wy1;
        float w10 = wx1 * wy0, w11 = wx1 * wy1;
        ax = w00 * (wz0 * v00.x + wz1 * v00.z)
           + w01 * (wz0 * v01.x + wz1 * v01.z)
           + w10 * (wz0 * v10.x + wz1 * v10.z)
           + w11 * (wz0 * v11.x + wz1 * v11.z);
        ay = w00 * (wz0 * v00.y + wz1 * v00.w)
           + w01 * (wz0 * v01.y + wz1 * v01.w)
           + w10 * (wz0 * v10.y + wz1 * v10.w)
           + w11 * (wz0 * v11.y + wz1 * v11.w);
    } else {
        // Hash path: 8 scattered 8B gathers.
        int z1 = iz + 1; if (z1 < 0) z1 += res; else if (z1 >= res) z1 -= res;
        unsigned hx[2], hy[2], hz[2];
        hx[0] = qval(x0, resf);
        hx[1] = qval(x1, resf);
        hy[0] = qval(y0, resf) * P1;
        hy[1] = qval(y1, resf) * P1;
        hz[0] = qval(z0, resf) * P2;
        hz[1] = qval(z1, resf) * P2;
        const float2* tab = tables + (size_t)level * TABLE_SIZE;
        float2 f[8];
#pragma unroll
        for (int c = 0; c < 8; c++) {
            unsigned idx = (hx[(c >> 2) & 1] + hy[(c >> 1) & 1] + hz[c & 1]) & HASH_MASK;
            f[c] = __ldg(&tab[idx]);
        }
        float wxa[2] = {wx0, wx1}, wya[2] = {wy0, wy1}, wza[2] = {wz0, wz1};
        ax = 0.0f; ay = 0.0f;
#pragma unroll
        for (int c = 0; c < 8; c++) {
            float w = wxa[(c >> 2) & 1] * wya[(c >> 1) & 1] * wza[c & 1];
            ax += w * f[c].x;
            ay += w * f[c].y;
        }
    }

    out[(size_t)point * 16 + level] = make_float2(ax, ay);
}

extern "C" void kernel_launch(void* const* d_in, const int* in_sizes, int n_in,
                              void* d_out, int out_size) {
    const float* x = (const float*)d_in[0];
    const float2* tables = (const float2*)d_in[1];
    float2* out = (float2*)d_out;
    int n_pts = in_sizes[0] / 3;

    // 1) build dense grids for levels 0..8 (largest is 101^3 = 1,030,301)
    dim3 pre_grid((1030301 + 255) / 256, N_SMALL);
    precompute_dense<<<pre_grid, 256>>>(tables);

    // 2) main encoding
    long long total = (long long)n_pts * 16;
    int grid = (int)((total + 255) / 256);
    hash_encoding_kernel<<<grid, 256>>>(x, tables, out, n_pts);
}